// round 17
// baseline (speedup 1.0000x reference)
#include <cuda_runtime.h>
#include <math.h>

#define S_SAMPLES 512
#define VDIM      128
#define NVOX      (VDIM * VDIM * VDIM)   // 2097152
#define NWORDS    (NVOX / 32)            // 65536 words per bitmap
#define DET       128
#define NPIX      (DET * DET)            // 16384

// Hybrid storage, natural (vx, vy, vz) indexing everywhere:
//  - FRONTAL volumes (view 0): BITMAPS. word = (vx*128+vy)*4 + vz/32, bit = vz&31.
//  - LATERAL volumes (view 1): BYTE volumes (coalesced lane stores along vz).
// gt float index = voxel index. Invariant: all zero at entry (static init +
// the reduce consumes-and-rezeroes everything it reads).
__device__ unsigned int g_bitsF[2][NWORDS];              // 512 KB
__device__ __align__(16) unsigned char g_volL[2][NVOX];  // 4 MB
__device__ double       g_acc = 0.0;
__device__ unsigned int g_ctr = 0;

// ---------------------------------------------------------------------------
// Backprojection: 128-thread blocks (512 blocks, 3.5/SM — finer granularity
// than the old 1.7/SM so the frontal/lateral cost asymmetry load-balances).
// Inner loop: combined bitwise bounds check ((vx|vy|vz) & ~127) == 0
// (negatives set high bits; >=128 sets bit 7) and 2x unroll.
// ---------------------------------------------------------------------------
__global__ void __launch_bounds__(128)
bp_kernel(const float* __restrict__ predF,
          const float* __restrict__ predL,
          const float* __restrict__ srcF,
          const float* __restrict__ tgtF,
          const float* __restrict__ srcL,
          const float* __restrict__ tgtL,
          const float* __restrict__ Ainv,
          const float* __restrict__ tinv)
{
    int p = blockIdx.x * blockDim.x + threadIdx.x;
    int slice = blockIdx.y;          // 0..3
    int view  = slice & 1;           // 0 = frontal, 1 = lateral
    int batch = slice >> 1;

    const float* mask = (view ? predL : predF) + batch * NPIX;
    if (!(mask[p] > 0.5f)) return;   // inactive pixel: nothing to do

    const float* src = view ? srcL : srcF;
    const float* tgt = (view ? tgtL : tgtF) + 3 * p;

    float sx = src[0], sy = src[1], sz = src[2];
    float dx = tgt[0] - sx, dy = tgt[1] - sy, dz = tgt[2] - sz;
    float len = sqrtf(dx * dx + dy * dy + dz * dz);
    float inv = 1.0f / (len + 1e-8f);
    dx *= inv; dy *= inv; dz *= inv;
    float L = len * 2.5f;

    float a00 = Ainv[0], a01 = Ainv[1], a02 = Ainv[2];
    float a10 = Ainv[3], a11 = Ainv[4], a12 = Ainv[5];
    float a20 = Ainv[6], a21 = Ainv[7], a22 = Ainv[8];

    // Voxel-space ray: q(t) = q0 + t*qd   (affine in t)
    float q0x = a00 * sx + a01 * sy + a02 * sz + tinv[0];
    float q0y = a10 * sx + a11 * sy + a12 * sz + tinv[1];
    float q0z = a20 * sx + a21 * sy + a22 * sz + tinv[2];
    float qdx = a00 * dx + a01 * dy + a02 * dz;
    float qdy = a10 * dx + a11 * dy + a12 * dz;
    float qdz = a20 * dx + a21 * dy + a22 * dz;

    const float LOQ = -0.501f;                  // round() valid window with margin
    const float HIQ = (float)VDIM - 0.499f;
    float tlo = 0.0f, thi = L;
    {
        float q0a[3] = {q0x, q0y, q0z};
        float qda[3] = {qdx, qdy, qdz};
        #pragma unroll
        for (int ax = 0; ax < 3; ax++) {
            float q0 = q0a[ax], qd = qda[ax];
            if (fabsf(qd) < 1e-9f) {
                if (q0 < LOQ || q0 > HIQ) { tlo = 1.0f; thi = 0.0f; }
            } else {
                float u1 = (LOQ - q0) / qd;
                float u2 = (HIQ - q0) / qd;
                tlo = fmaxf(tlo, fminf(u1, u2));
                thi = fminf(thi, fmaxf(u1, u2));
            }
        }
    }
    if (thi < tlo) return;

    float dt = L * (1.0f / (S_SAMPLES - 1));
    int klo = max(0,             (int)floorf(tlo / dt) - 2);   // safety margin:
    int khi = min(S_SAMPLES - 1, (int)ceilf (thi / dt) + 2);   // per-sample check authoritative

    float rdx = L * qdx, rdy = L * qdy, rdz = L * qdz;
    const float c1 = 1.0f / (S_SAMPLES - 1);

    if (view == 0) {
        // ---- frontal: bitmap with register-accumulated REDG.OR flush -------
        unsigned int* bits = g_bitsF[batch];
        int prevw = -1;
        unsigned int acc = 0u;
        #pragma unroll 2
        for (int k = klo; k <= khi; k++) {
            float tv = (float)k * c1;                      // jnp.linspace(0,1,S)
            int vx = __float2int_rn(fmaf(tv, rdx, q0x));   // ties-to-even = jnp.round
            int vy = __float2int_rn(fmaf(tv, rdy, q0y));
            int vz = __float2int_rn(fmaf(tv, rdz, q0z));
            if (((vx | vy | vz) & ~(VDIM - 1)) == 0) {     // all in [0,128)
                int word = (((vx << 7) + vy) << 2) + (vz >> 5);
                unsigned int b = 1u << (vz & 31);
                if (word == prevw) {
                    acc |= b;                              // same word: local OR
                } else {
                    if (prevw >= 0) atomicOr(&bits[prevw], acc);   // REDG.OR
                    prevw = word;
                    acc = b;
                }
            }
        }
        if (prevw >= 0) atomicOr(&bits[prevw], acc);
    } else {
        // ---- lateral: byte volume, coalesced idempotent stores -------------
        unsigned char* vol = g_volL[batch];
        #pragma unroll 2
        for (int k = klo; k <= khi; k++) {
            float tv = (float)k * c1;
            int vx = __float2int_rn(fmaf(tv, rdx, q0x));
            int vy = __float2int_rn(fmaf(tv, rdy, q0y));
            int vz = __float2int_rn(fmaf(tv, rdz, q0z));
            if (((vx | vy | vz) & ~(VDIM - 1)) == 0) {     // all in [0,128)
                vol[(vx * VDIM + vy) * VDIM + vz] = 1;   // lanes contiguous in vz
            }
        }
    }
}

// ---------------------------------------------------------------------------
// BCE + finalize + re-zero (R16 body). Grid (128, 8) x 256 threads = 1024
// blocks; one thread per 8 vz voxels.
//   (CC+g)*s0 + (CC+g)*s1 = (CC+g)*s01,  s01 bytewise sum <= 4 (carry-free).
// ---------------------------------------------------------------------------
#define CC_F    (-0.62011450695827750f)   // b1 - b0
#define KAPPA_F (-0.19355181656647243f)   // b2 - 2*b1 + b0
#define B0_D    (-0.69314718055994531)    // log(0.5)

__device__ __forceinline__ float warp_sum(float v) {
    #pragma unroll
    for (int o = 16; o > 0; o >>= 1) v += __shfl_down_sync(0xffffffffu, v, o);
    return v;
}

__global__ void __launch_bounds__(256)
reduce_kernel(const float* __restrict__ gt, float* __restrict__ out)
{
    __shared__ float sh[8];
    int t  = threadIdx.x;
    int vx = blockIdx.x;
    int vy = blockIdx.y * 16 + (t >> 4);
    int o  = t & 15;                      // vz octet: vz = 8o .. 8o+7
    int row   = (vx << 7) + vy;           // vx*128 + vy
    int w32   = (row << 2) + (o >> 2);    // frontal word index
    int bsel  = o & 3;                    // byte within frontal word
    int lbase = (row << 5) + (o << 1);    // lateral/gt 4B-word index (2 words)
    int l64   = (row << 4) + o;           // lateral uint2 index

    // ---- issue ALL loads up front (MLP 6) ---------------------------------
    unsigned int F0 = g_bitsF[0][w32];
    unsigned int F1 = g_bitsF[1][w32];
    uint2 L0 = reinterpret_cast<const uint2*>(g_volL[0])[l64];
    uint2 L1 = reinterpret_cast<const uint2*>(g_volL[1])[l64];
    float4 gv[2];
    gv[0] = reinterpret_cast<const float4*>(gt)[lbase + 0];
    gv[1] = reinterpret_cast<const float4*>(gt)[lbase + 1];

    // ---- consume-and-reset ------------------------------------------------
    // Frontal word shared by 4 consecutive threads of ONE warp (same vy row);
    // their LDGs precede this STG in the warp's in-order stream.
    if (bsel == 0) {
        g_bitsF[0][w32] = 0u;
        g_bitsF[1][w32] = 0u;
    }
    uint2 z2; z2.x = 0u; z2.y = 0u;
    reinterpret_cast<uint2*>(g_volL[0])[l64] = z2;
    reinterpret_cast<uint2*>(g_volL[1])[l64] = z2;

    // ---- this thread's 8-bit frontal slices -------------------------------
    int shft = bsel << 3;
    unsigned int f0b = (F0 >> shft) & 0xffu;
    unsigned int f1b = (F1 >> shft) & 0xffu;

    // ---- compute (pure register math) -------------------------------------
    unsigned int l0w[2] = { L0.x, L0.y };
    unsigned int l1w[2] = { L1.x, L1.y };
    float sum  = 0.0f;
    int   icnt = 0;
    #pragma unroll
    for (int q = 0; q < 2; q++) {
        unsigned int fw0 = (((f0b >> (4 * q)) & 0xFu) * 0x00204081u) & 0x01010101u;
        unsigned int fw1 = (((f1b >> (4 * q)) & 0xFu) * 0x00204081u) & 0x01010101u;
        icnt += __popc(l0w[q] & fw0) + __popc(l1w[q] & fw1);   // intersections
        // combined bytewise count across BOTH batches (bytes <= 4, carry-free)
        unsigned int s01 = (l0w[q] + l1w[q]) + (fw0 + fw1);
        sum = fmaf((float)( s01        & 255u), CC_F + gv[q].x, sum);
        sum = fmaf((float)((s01 >>  8) & 255u), CC_F + gv[q].y, sum);
        sum = fmaf((float)((s01 >> 16) & 255u), CC_F + gv[q].z, sum);
        sum = fmaf((float)( s01 >> 24        ), CC_F + gv[q].w, sum);
    }
    sum = fmaf(KAPPA_F, (float)icnt, sum);

    // ---- block reduce -> global atomic -> last-block finalize -------------
    sum = warp_sum(sum);
    int lane = t & 31, w = t >> 5;
    if (lane == 0) sh[w] = sum;
    __syncthreads();
    if (w == 0) {
        float v = (lane < 8) ? sh[lane] : 0.0f;
        v = warp_sum(v);
        if (lane == 0) {
            atomicAdd(&g_acc, (double)v);
            __threadfence();
            unsigned int total = gridDim.x * gridDim.y;
            unsigned int done = atomicInc(&g_ctr, total - 1);   // self-resetting
            if (done == total - 1) {
                double acc = atomicAdd(&g_acc, 0.0);            // atomic read
                // loss = -( 2*NVOX*B0 + acc ) / (2*NVOX) = -B0 - acc/(2*NVOX)
                out[0] = (float)(-B0_D - acc / (2.0 * (double)NVOX));
                g_acc = 0.0;                                    // reset for next call
            }
        }
    }
}

// ---------------------------------------------------------------------------
extern "C" void kernel_launch(void* const* d_in, const int* in_sizes, int n_in,
                              void* d_out, int out_size)
{
    const float* predF = (const float*)d_in[0];
    const float* predL = (const float*)d_in[1];
    const float* srcF  = (const float*)d_in[2];
    const float* tgtF  = (const float*)d_in[3];
    const float* srcL  = (const float*)d_in[4];
    const float* tgtL  = (const float*)d_in[5];
    const float* gt    = (const float*)d_in[6];
    const float* Ainv  = (const float*)d_in[7];
    const float* tinv  = (const float*)d_in[8];
    float* out = (float*)d_out;

    dim3 bp_grid(NPIX / 128, 4);              // 128 x 4 = 512 blocks x 128 threads
    bp_kernel<<<bp_grid, 128>>>(predF, predL, srcF, tgtF, srcL, tgtL, Ainv, tinv);

    dim3 rd_grid(VDIM, 8);                    // 1024 blocks x 256 threads
    reduce_kernel<<<rd_grid, 256>>>(gt, out);
}